// round 1
// baseline (speedup 1.0000x reference)
#include <cuda_runtime.h>

// Sinkhorn on s[B=32, N=1024, M=1024], MAX_ITER=15, EPS=1e-4.
// Factored form: s_t = r_i * s0_ij * c_j. Only reductions over the constant
// input matrix are needed per iteration; the matrix is never rewritten.

#define BB 32
#define NN 1024
#define MM 1024
#define EPSF 1e-4f
#define ISPLIT 4

__device__ float g_r[BB * NN];
__device__ float g_c[BB * MM];
__device__ float g_part[BB * ISPLIT * MM];

// ---------------------------------------------------------------------------
__global__ void init_rc_kernel() {
    int idx = blockIdx.x * blockDim.x + threadIdx.x;
    if (idx < BB * NN) g_r[idx] = 1.0f;
    if (idx < BB * MM) g_c[idx] = 1.0f;
}

// ---------------------------------------------------------------------------
// Column-sum partial: P_part[b, split, j] = sum_{i in split} r[b,i] * s[b,i,j]
// grid: (MM/256, ISPLIT, BB), block: 256 threads (one column j per thread).
__global__ void col_partial_kernel(const float* __restrict__ s) {
    const int b = blockIdx.z;
    const int split = blockIdx.y;
    const int j = blockIdx.x * 256 + threadIdx.x;
    const int ROWS = NN / ISPLIT;  // 256
    const int i0 = split * ROWS;

    __shared__ float sh_r[NN / ISPLIT];
    for (int i = threadIdx.x; i < ROWS; i += 256)
        sh_r[i] = g_r[b * NN + i0 + i];
    __syncthreads();

    const float* sp = s + (size_t)b * NN * MM + (size_t)i0 * MM + j;

    float a0 = 0.f, a1 = 0.f, a2 = 0.f, a3 = 0.f;
#pragma unroll 8
    for (int i = 0; i < ROWS; i += 4) {
        a0 = fmaf(sh_r[i + 0], sp[(size_t)(i + 0) * MM], a0);
        a1 = fmaf(sh_r[i + 1], sp[(size_t)(i + 1) * MM], a1);
        a2 = fmaf(sh_r[i + 2], sp[(size_t)(i + 2) * MM], a2);
        a3 = fmaf(sh_r[i + 3], sp[(size_t)(i + 3) * MM], a3);
    }
    g_part[((size_t)b * ISPLIT + split) * MM + j] = (a0 + a1) + (a2 + a3);
}

// Combine partials and update c:  c_j <- c_j / (c_j * P_j + eps)
__global__ void col_finish_kernel() {
    int idx = blockIdx.x * blockDim.x + threadIdx.x;  // b*MM + j
    if (idx >= BB * MM) return;
    int b = idx / MM;
    int j = idx - b * MM;
    float p = 0.f;
#pragma unroll
    for (int k = 0; k < ISPLIT; k++)
        p += g_part[((size_t)b * ISPLIT + k) * MM + j];
    float c = g_c[idx];
    g_c[idx] = c / fmaf(c, p, EPSF);
}

// ---------------------------------------------------------------------------
// Row step: Q_i = sum_j s[b,i,j] * c[b,j];  r_i <- r_i / (r_i*Q_i + eps)
// grid: (NN/8, BB), block: 256 threads = 8 warps, one row per warp.
__global__ void row_step_kernel(const float* __restrict__ s) {
    const int b = blockIdx.y;
    const int warp = threadIdx.x >> 5;
    const int lane = threadIdx.x & 31;
    const int i = blockIdx.x * 8 + warp;

    __shared__ float sh_c[MM];
    for (int k = threadIdx.x; k < MM; k += 256)
        sh_c[k] = g_c[b * MM + k];
    __syncthreads();

    const float4* sp =
        (const float4*)(s + (size_t)b * NN * MM + (size_t)i * MM);

    float acc = 0.f;
#pragma unroll
    for (int k = 0; k < MM / 128; k++) {  // 8 float4 loads per lane
        int idx4 = k * 32 + lane;
        float4 v = sp[idx4];
        int jj = idx4 * 4;
        acc = fmaf(v.x, sh_c[jj + 0], acc);
        acc = fmaf(v.y, sh_c[jj + 1], acc);
        acc = fmaf(v.z, sh_c[jj + 2], acc);
        acc = fmaf(v.w, sh_c[jj + 3], acc);
    }
#pragma unroll
    for (int o = 16; o > 0; o >>= 1)
        acc += __shfl_xor_sync(0xffffffffu, acc, o);

    if (lane == 0) {
        float r = g_r[b * NN + i];
        g_r[b * NN + i] = r / fmaf(r, acc, EPSF);
    }
}

// ---------------------------------------------------------------------------
// Final: out = r_i * s0_ij * c_j.  grid: (NN/8, BB), 256 threads; one block
// covers 8 full rows (256 float4 per row).
__global__ void finalize_kernel(const float* __restrict__ s,
                                float* __restrict__ out) {
    const int b = blockIdx.y;
    const int i0 = blockIdx.x * 8;

    __shared__ float4 sh_c4[MM / 4];
    {
        const float4* cg = (const float4*)(g_c + (size_t)b * MM);
        sh_c4[threadIdx.x] = cg[threadIdx.x];
    }
    __syncthreads();

    const float4 c4 = sh_c4[threadIdx.x];

#pragma unroll
    for (int w = 0; w < 8; w++) {
        const int i = i0 + w;
        const float r = g_r[b * NN + i];
        const float4* sp =
            (const float4*)(s + (size_t)b * NN * MM + (size_t)i * MM);
        float4* op = (float4*)(out + (size_t)b * NN * MM + (size_t)i * MM);
        float4 v = sp[threadIdx.x];
        float4 o;
        o.x = r * v.x * c4.x;
        o.y = r * v.y * c4.y;
        o.z = r * v.z * c4.z;
        o.w = r * v.w * c4.w;
        op[threadIdx.x] = o;
    }
}

// ---------------------------------------------------------------------------
extern "C" void kernel_launch(void* const* d_in, const int* in_sizes, int n_in,
                              void* d_out, int out_size) {
    const float* s = (const float*)d_in[0];
    float* out = (float*)d_out;

    init_rc_kernel<<<(BB * NN + 255) / 256, 256>>>();

    for (int it = 0; it < 15; it++) {
        if ((it & 1) == 0) {
            // axis=1: column sums
            col_partial_kernel<<<dim3(MM / 256, ISPLIT, BB), 256>>>(s);
            col_finish_kernel<<<(BB * MM + 255) / 256, 256>>>();
        } else {
            // axis=2: row sums
            row_step_kernel<<<dim3(NN / 8, BB), 256>>>(s);
        }
    }

    finalize_kernel<<<dim3(NN / 8, BB), 256>>>(s, out);
}

// round 2
// speedup vs baseline: 1.3192x; 1.3192x over previous
#include <cuda_runtime.h>
#include <cuda_fp16.h>

// Sinkhorn on s[B=32, N=1024, M=1024], MAX_ITER=15, EPS=1e-4.
// Factored form: s_t = r_i * s0_ij * c_j. Reductions run over a one-time
// fp16 copy of s0 (64 MB -> fits in the 126 MB L2, so passes 2..15 are
// L2-resident). Final output uses the original fp32 s0 for full precision.

#define BB 32
#define NN 1024
#define MM 1024
#define EPSF 1e-4f
#define ISPLIT 8

__device__ __half2 g_h[(size_t)BB * NN * MM / 2];  // 64 MB fp16 copy
__device__ float g_r[BB * NN];
__device__ float g_c[BB * MM];
__device__ float g_part[BB * ISPLIT * MM];

// ---------------------------------------------------------------------------
__global__ void init_rc_kernel() {
    int idx = blockIdx.x * blockDim.x + threadIdx.x;
    if (idx < BB * NN) g_r[idx] = 1.0f;
    if (idx < BB * MM) g_c[idx] = 1.0f;
}

// ---------------------------------------------------------------------------
// One-time fp32 -> fp16 conversion. Each thread converts 8 floats -> 1 uint4.
__global__ void conv_kernel(const float4* __restrict__ s4) {
    size_t idx = (size_t)blockIdx.x * blockDim.x + threadIdx.x;
    // total threads = BB*NN*MM/8 = 4M
    float4 a = s4[2 * idx];
    float4 b = s4[2 * idx + 1];
    __half2 h0 = __floats2half2_rn(a.x, a.y);
    __half2 h1 = __floats2half2_rn(a.z, a.w);
    __half2 h2 = __floats2half2_rn(b.x, b.y);
    __half2 h3 = __floats2half2_rn(b.z, b.w);
    uint4 o;
    o.x = *(unsigned*)&h0;
    o.y = *(unsigned*)&h1;
    o.z = *(unsigned*)&h2;
    o.w = *(unsigned*)&h3;
    ((uint4*)g_h)[idx] = o;
}

// ---------------------------------------------------------------------------
// Column-sum partial over fp16 copy:
//   P_part[b, split, j] = sum_{i in split} r[b,i] * s0[b,i,j]
// grid: (MM/512, ISPLIT, BB), block: 256 threads (one half2 col-pair each).
__global__ void col_partial_kernel() {
    const int b = blockIdx.z;
    const int split = blockIdx.y;
    const int j2 = blockIdx.x * 256 + threadIdx.x;  // half2 column index
    const int ROWS = NN / ISPLIT;                   // 128
    const int i0 = split * ROWS;

    __shared__ float sr[NN / ISPLIT];
    if (threadIdx.x < ROWS) sr[threadIdx.x] = g_r[b * NN + i0 + threadIdx.x];
    __syncthreads();

    const __half2* hp = g_h + ((size_t)(b * NN + i0)) * (MM / 2) + j2;

    float ax0 = 0.f, ay0 = 0.f, ax1 = 0.f, ay1 = 0.f;
#pragma unroll 4
    for (int i = 0; i < ROWS; i += 2) {
        __half2 v0 = hp[(size_t)i * (MM / 2)];
        __half2 v1 = hp[(size_t)(i + 1) * (MM / 2)];
        float2 f0 = __half22float2(v0);
        float2 f1 = __half22float2(v1);
        ax0 = fmaf(sr[i], f0.x, ax0);
        ay0 = fmaf(sr[i], f0.y, ay0);
        ax1 = fmaf(sr[i + 1], f1.x, ax1);
        ay1 = fmaf(sr[i + 1], f1.y, ay1);
    }
    float* pp = g_part + ((size_t)(b * ISPLIT + split)) * MM + 2 * j2;
    pp[0] = ax0 + ax1;
    pp[1] = ay0 + ay1;
}

// Combine partials, update c:  c_j <- c_j / (c_j * P_j + eps)
__global__ void col_finish_kernel() {
    int idx = blockIdx.x * blockDim.x + threadIdx.x;  // b*MM + j
    if (idx >= BB * MM) return;
    int b = idx >> 10;
    int j = idx & (MM - 1);
    float p = 0.f;
#pragma unroll
    for (int k = 0; k < ISPLIT; k++)
        p += g_part[((size_t)(b * ISPLIT + k)) * MM + j];
    float c = g_c[idx];
    g_c[idx] = c / fmaf(c, p, EPSF);
}

// ---------------------------------------------------------------------------
// Row step over fp16 copy: Q_i = sum_j s0[b,i,j]*c[b,j];
//   r_i <- r_i / (r_i*Q_i + eps)
// grid: (NN/8, BB), block: 256 = 8 warps, warp per row. Row = 128 uint4.
__global__ void row_step_kernel() {
    const int b = blockIdx.y;
    const int warp = threadIdx.x >> 5;
    const int lane = threadIdx.x & 31;
    const int i = blockIdx.x * 8 + warp;

    __shared__ float sh_c[MM];
    for (int k = threadIdx.x; k < MM; k += 256)
        sh_c[k] = g_c[b * MM + k];
    __syncthreads();

    const uint4* hp = (const uint4*)(g_h + ((size_t)(b * NN + i)) * (MM / 2));

    float acc = 0.f;
#pragma unroll
    for (int k = 0; k < 4; k++) {  // 4 x 16B per lane = 32 halfs
        int v4 = k * 32 + lane;
        uint4 v = hp[v4];
        int jj = v4 * 8;
        __half2 h0 = *(__half2*)&v.x;
        __half2 h1 = *(__half2*)&v.y;
        __half2 h2 = *(__half2*)&v.z;
        __half2 h3 = *(__half2*)&v.w;
        float2 f0 = __half22float2(h0);
        float2 f1 = __half22float2(h1);
        float2 f2 = __half22float2(h2);
        float2 f3 = __half22float2(h3);
        acc = fmaf(f0.x, sh_c[jj + 0], acc);
        acc = fmaf(f0.y, sh_c[jj + 1], acc);
        acc = fmaf(f1.x, sh_c[jj + 2], acc);
        acc = fmaf(f1.y, sh_c[jj + 3], acc);
        acc = fmaf(f2.x, sh_c[jj + 4], acc);
        acc = fmaf(f2.y, sh_c[jj + 5], acc);
        acc = fmaf(f3.x, sh_c[jj + 6], acc);
        acc = fmaf(f3.y, sh_c[jj + 7], acc);
    }
#pragma unroll
    for (int o = 16; o > 0; o >>= 1)
        acc += __shfl_xor_sync(0xffffffffu, acc, o);

    if (lane == 0) {
        float r = g_r[b * NN + i];
        g_r[b * NN + i] = r / fmaf(r, acc, EPSF);
    }
}

// ---------------------------------------------------------------------------
// Final: out = r_i * s0_ij * c_j from the ORIGINAL fp32 s0 (full precision).
// grid: (NN/8, BB), 256 threads; block covers 8 rows (256 float4 per row).
__global__ void finalize_kernel(const float* __restrict__ s,
                                float* __restrict__ out) {
    const int b = blockIdx.y;
    const int i0 = blockIdx.x * 8;

    __shared__ float4 sh_c4[MM / 4];
    {
        const float4* cg = (const float4*)(g_c + (size_t)b * MM);
        sh_c4[threadIdx.x] = cg[threadIdx.x];
    }
    __syncthreads();

    const float4 c4 = sh_c4[threadIdx.x];

#pragma unroll
    for (int w = 0; w < 8; w++) {
        const int i = i0 + w;
        const float r = g_r[b * NN + i];
        const float4* sp =
            (const float4*)(s + (size_t)b * NN * MM + (size_t)i * MM);
        float4* op = (float4*)(out + (size_t)b * NN * MM + (size_t)i * MM);
        float4 v = sp[threadIdx.x];
        float4 o;
        o.x = r * v.x * c4.x;
        o.y = r * v.y * c4.y;
        o.z = r * v.z * c4.z;
        o.w = r * v.w * c4.w;
        op[threadIdx.x] = o;
    }
}

// ---------------------------------------------------------------------------
extern "C" void kernel_launch(void* const* d_in, const int* in_sizes, int n_in,
                              void* d_out, int out_size) {
    const float* s = (const float*)d_in[0];
    float* out = (float*)d_out;

    init_rc_kernel<<<(BB * NN + 255) / 256, 256>>>();
    conv_kernel<<<(BB * NN * MM / 8) / 256, 256>>>((const float4*)s);

    for (int it = 0; it < 15; it++) {
        if ((it & 1) == 0) {
            col_partial_kernel<<<dim3(MM / 512, ISPLIT, BB), 256>>>();
            col_finish_kernel<<<(BB * MM + 255) / 256, 256>>>();
        } else {
            row_step_kernel<<<dim3(NN / 8, BB), 256>>>();
        }
    }

    finalize_kernel<<<dim3(NN / 8, BB), 256>>>(s, out);
}

// round 3
// speedup vs baseline: 1.3849x; 1.0498x over previous
#include <cuda_runtime.h>
#include <cuda_fp16.h>

// Sinkhorn on s[B=32, N=1024, M=1024], MAX_ITER=15, EPS=1e-4.
// Factored form: s_t = r_i * s0_ij * c_j. Reductions run over a one-time
// fp16 copy of s0 (64 MB, L2-resident). Column steps own whole columns per
// block and update c in-block (no partials / finish kernel).

#define BB 32
#define NN 1024
#define MM 1024
#define EPSF 1e-4f

__device__ __half2 g_h[(size_t)BB * NN * MM / 2];  // 64 MB fp16 copy
__device__ float g_r[BB * NN];
__device__ float g_c[BB * MM];

// ---------------------------------------------------------------------------
// One-time fp32 -> fp16 conversion (8 floats -> 1 uint4 per thread).
// Also initializes r and c to 1.
__global__ void conv_kernel(const float4* __restrict__ s4) {
    size_t idx = (size_t)blockIdx.x * blockDim.x + threadIdx.x;
    if (idx < BB * NN) g_r[idx] = 1.0f;
    if (idx < BB * MM) g_c[idx] = 1.0f;
    float4 a = s4[2 * idx];
    float4 b = s4[2 * idx + 1];
    __half2 h0 = __floats2half2_rn(a.x, a.y);
    __half2 h1 = __floats2half2_rn(a.z, a.w);
    __half2 h2 = __floats2half2_rn(b.x, b.y);
    __half2 h3 = __floats2half2_rn(b.z, b.w);
    uint4 o;
    o.x = *(unsigned*)&h0;
    o.y = *(unsigned*)&h1;
    o.z = *(unsigned*)&h2;
    o.w = *(unsigned*)&h3;
    ((uint4*)g_h)[idx] = o;
}

// ---------------------------------------------------------------------------
// Column step, fully fused:
//   P_j = sum_i r[b,i] * s0[b,i,j];  c_j <- c_j / (c_j * P_j + eps)
// Block owns 64 complete columns. 256 threads = 8 col-uint4 x 32 row-strips
// of 32 rows. grid: (MM/64 = 16, BB).
__global__ void col_step_kernel() {
    const int b = blockIdx.y;
    const int j0 = blockIdx.x * 64;           // first column of this block
    const int cu = threadIdx.x & 7;           // which uint4 (8 cols) in group
    const int rg = threadIdx.x >> 3;          // row strip 0..31 (32 rows each)

    __shared__ float sr[NN];                  // 4 KB row weights
    for (int k = threadIdx.x; k < NN; k += 256)
        sr[k] = g_r[b * NN + k];
    __syncthreads();

    // row stride in uint4 units: MM halfs / 8 = 128
    const uint4* p = (const uint4*)g_h +
                     (size_t)b * NN * (MM / 8) +
                     (size_t)(rg * 32) * (MM / 8) + (j0 >> 3) + cu;

    float acc[8];
#pragma unroll
    for (int k = 0; k < 8; k++) acc[k] = 0.f;

#pragma unroll 4
    for (int i = 0; i < 32; i++) {
        uint4 v = p[(size_t)i * (MM / 8)];
        float rw = sr[rg * 32 + i];
        __half2 h0 = *(__half2*)&v.x;
        __half2 h1 = *(__half2*)&v.y;
        __half2 h2 = *(__half2*)&v.z;
        __half2 h3 = *(__half2*)&v.w;
        float2 f0 = __half22float2(h0);
        float2 f1 = __half22float2(h1);
        float2 f2 = __half22float2(h2);
        float2 f3 = __half22float2(h3);
        acc[0] = fmaf(rw, f0.x, acc[0]);
        acc[1] = fmaf(rw, f0.y, acc[1]);
        acc[2] = fmaf(rw, f1.x, acc[2]);
        acc[3] = fmaf(rw, f1.y, acc[3]);
        acc[4] = fmaf(rw, f2.x, acc[4]);
        acc[5] = fmaf(rw, f2.y, acc[5]);
        acc[6] = fmaf(rw, f3.x, acc[6]);
        acc[7] = fmaf(rw, f3.y, acc[7]);
    }

    __shared__ float sacc[32][64];            // 8 KB strip partials
#pragma unroll
    for (int k = 0; k < 8; k++) sacc[rg][cu * 8 + k] = acc[k];
    __syncthreads();

    if (threadIdx.x < 64) {
        float pps = 0.f;
#pragma unroll
        for (int r2 = 0; r2 < 32; r2++) pps += sacc[r2][threadIdx.x];
        const int idx = b * MM + j0 + threadIdx.x;
        float c = g_c[idx];
        g_c[idx] = c / fmaf(c, pps, EPSF);
    }
}

// ---------------------------------------------------------------------------
// Row step: Q_i = sum_j s0[b,i,j]*c[b,j];  r_i <- r_i / (r_i*Q_i + eps)
// grid: (NN/8, BB), block 256 = 8 warps, one row per warp (128 uint4/row).
__global__ void row_step_kernel() {
    const int b = blockIdx.y;
    const int warp = threadIdx.x >> 5;
    const int lane = threadIdx.x & 31;
    const int i = blockIdx.x * 8 + warp;

    __shared__ float sh_c[MM];
    for (int k = threadIdx.x; k < MM; k += 256)
        sh_c[k] = g_c[b * MM + k];
    __syncthreads();

    const uint4* hp = (const uint4*)(g_h + ((size_t)(b * NN + i)) * (MM / 2));

    float acc = 0.f;
#pragma unroll
    for (int k = 0; k < 4; k++) {  // 4 x 16B per lane = 32 halfs
        int v4 = k * 32 + lane;
        uint4 v = hp[v4];
        int jj = v4 * 8;
        __half2 h0 = *(__half2*)&v.x;
        __half2 h1 = *(__half2*)&v.y;
        __half2 h2 = *(__half2*)&v.z;
        __half2 h3 = *(__half2*)&v.w;
        float2 f0 = __half22float2(h0);
        float2 f1 = __half22float2(h1);
        float2 f2 = __half22float2(h2);
        float2 f3 = __half22float2(h3);
        acc = fmaf(f0.x, sh_c[jj + 0], acc);
        acc = fmaf(f0.y, sh_c[jj + 1], acc);
        acc = fmaf(f1.x, sh_c[jj + 2], acc);
        acc = fmaf(f1.y, sh_c[jj + 3], acc);
        acc = fmaf(f2.x, sh_c[jj + 4], acc);
        acc = fmaf(f2.y, sh_c[jj + 5], acc);
        acc = fmaf(f3.x, sh_c[jj + 6], acc);
        acc = fmaf(f3.y, sh_c[jj + 7], acc);
    }
#pragma unroll
    for (int o = 16; o > 0; o >>= 1)
        acc += __shfl_xor_sync(0xffffffffu, acc, o);

    if (lane == 0) {
        float r = g_r[b * NN + i];
        g_r[b * NN + i] = r / fmaf(r, acc, EPSF);
    }
}

// ---------------------------------------------------------------------------
// Final: out = r_i * s0_ij * c_j from the ORIGINAL fp32 s0 (full precision).
// grid: (NN/8, BB), 256 threads; block covers 8 rows (256 float4 per row).
__global__ void finalize_kernel(const float* __restrict__ s,
                                float* __restrict__ out) {
    const int b = blockIdx.y;
    const int i0 = blockIdx.x * 8;

    __shared__ float4 sh_c4[MM / 4];
    {
        const float4* cg = (const float4*)(g_c + (size_t)b * MM);
        sh_c4[threadIdx.x] = cg[threadIdx.x];
    }
    __syncthreads();

    const float4 c4 = sh_c4[threadIdx.x];

#pragma unroll
    for (int w = 0; w < 8; w++) {
        const int i = i0 + w;
        const float r = g_r[b * NN + i];
        const float4* sp =
            (const float4*)(s + (size_t)b * NN * MM + (size_t)i * MM);
        float4* op = (float4*)(out + (size_t)b * NN * MM + (size_t)i * MM);
        float4 v = sp[threadIdx.x];
        float4 o;
        o.x = r * v.x * c4.x;
        o.y = r * v.y * c4.y;
        o.z = r * v.z * c4.z;
        o.w = r * v.w * c4.w;
        op[threadIdx.x] = o;
    }
}

// ---------------------------------------------------------------------------
extern "C" void kernel_launch(void* const* d_in, const int* in_sizes, int n_in,
                              void* d_out, int out_size) {
    const float* s = (const float*)d_in[0];
    float* out = (float*)d_out;

    conv_kernel<<<(BB * NN * MM / 8) / 256, 256>>>((const float4*)s);

    for (int it = 0; it < 15; it++) {
        if ((it & 1) == 0) {
            col_step_kernel<<<dim3(MM / 64, BB), 256>>>();
        } else {
            row_step_kernel<<<dim3(NN / 8, BB), 256>>>();
        }
    }

    finalize_kernel<<<dim3(NN / 8, BB), 256>>>(s, out);
}